// round 5
// baseline (speedup 1.0000x reference)
#include <cuda_runtime.h>

#define N_NODES 100000
#define N_EDGES 1600000
#define DIM 128
#define EDIM 16
#define NBLK 98             // ceil(100000/1024)
#define LOGIT_BLOCKS 2500   // 2500*8 warps * 80 edges = 1.6M
#define EDGES_PER_WARP 80

typedef unsigned long long u64;

// f32x2 packed math (sm_103a; ptxas never auto-fuses these)
#define FMA2(d, a, b, c) asm("fma.rn.f32x2 %0, %1, %2, %3;" : "=l"(d) : "l"(a), "l"(b), "l"(c))
#define ADD2(d, a, b)    asm("add.rn.f32x2 %0, %1, %2;"     : "=l"(d) : "l"(a), "l"(b))
#define PACK2(d, lo, hi) asm("mov.b64 %0, {%1, %2};" : "=l"(d) : "r"(__float_as_uint(lo)), "r"(__float_as_uint(hi)))
#define UNPK2(lo, hi, v) do { unsigned _ulo, _uhi; asm("mov.b64 {%0, %1}, %2;" : "=r"(_ulo), "=r"(_uhi) : "l"(v)); lo = __uint_as_float(_ulo); hi = __uint_as_float(_uhi); } while (0)

// ---------------- static scratch (no allocations allowed) ----------------
__device__ __align__(16) float g_h[N_NODES * DIM];    // node features between layers
__device__ __align__(16) float g_gl[N_NODES * DIM];   // x @ Wl + bl
__device__ __align__(16) float g_gr[N_NODES * DIM];   // x @ Wr + br
__device__ __align__(16) float g_w[N_EDGES * 4];      // per-edge per-head exp(logit)
__device__ int   g_cnt[N_NODES];                      // zero at load; re-zeroed by scan1
__device__ int   g_off[N_NODES + 1];
__device__ int   g_cursor[N_NODES];
__device__ int   g_bsum[128];
__device__ __align__(16) int2 g_einfo[N_EDGES];       // (src, edge_id) sorted by dst
__device__ float g_stats[2 * DIM];                    // sum | sumsq (re-zeroed by bn_finalize)
__device__ float g_bnp[2 * DIM];                      // scale | shift

// ---------------- CSR build ----------------
// edge_index is INT32 (JAX x64-disabled downcast)
__global__ void k_hist(const int* __restrict__ ei, int* __restrict__ cnt) {
    int e = blockIdx.x * blockDim.x + threadIdx.x;
    if (e < N_EDGES) atomicAdd(&cnt[ei[N_EDGES + e]], 1);
}

__global__ void k_scan1(int* __restrict__ cnt, int* __restrict__ off,
                        int* __restrict__ bsum) {
    __shared__ int s[1024];
    int tid = threadIdx.x;
    int i = blockIdx.x * 1024 + tid;
    int v = (i < N_NODES) ? cnt[i] : 0;
    if (i < N_NODES) cnt[i] = 0;           // re-zero for next call
    s[tid] = v; __syncthreads();
    for (int d = 1; d < 1024; d <<= 1) {
        int t = (tid >= d) ? s[tid - d] : 0;
        __syncthreads();
        s[tid] += t;
        __syncthreads();
    }
    if (i < N_NODES) off[i] = s[tid] - v;   // exclusive within block
    if (tid == 1023) bsum[blockIdx.x] = s[1023];
}

__global__ void k_scan23(int* __restrict__ off, const int* __restrict__ bsum,
                         int* __restrict__ cursor) {
    __shared__ int sp[NBLK];
    int tid = threadIdx.x;
    if (tid == 0) {
        int acc = 0;
        for (int b = 0; b < NBLK; b++) { sp[b] = acc; acc += bsum[b]; }
    }
    __syncthreads();
    int i = blockIdx.x * blockDim.x + tid;
    if (i < N_NODES) {
        int o = off[i] + sp[i >> 10];
        off[i] = o;
        cursor[i] = o;
    }
    if (i == 0) off[N_NODES] = N_EDGES;
}

__global__ void k_scatter(const int* __restrict__ ei, int* __restrict__ cursor,
                          int2* __restrict__ einfo) {
    int e = blockIdx.x * blockDim.x + threadIdx.x;
    if (e < N_EDGES) {
        int src = ei[e];
        int dst = ei[N_EDGES + e];
        int pos = atomicAdd(&cursor[dst], 1);
        einfo[pos] = make_int2(src, e);
    }
}

// ---------------- dual node GEMM (f32x2): gl = f(h)@Wl+bl, gr = f(h)@Wr+br ----
#define SXS 20
__global__ __launch_bounds__(128) void k_gemm_dual(
    const float* __restrict__ h, int applyBN, const float* __restrict__ bnp,
    const float* __restrict__ Wl, const float* __restrict__ bl,
    const float* __restrict__ Wr, const float* __restrict__ br,
    float* __restrict__ gl, float* __restrict__ gr)
{
    __shared__ __align__(16) float sx[128 * SXS];
    __shared__ float sSc[DIM], sSh[DIM];
    int tid = threadIdx.x;
    sSc[tid] = bnp[tid];
    sSh[tid] = bnp[DIM + tid];
    __syncthreads();
    int n0 = blockIdx.x * 16;
    {
        int k = tid;
        float sc = sSc[k], sh = sSh[k];
#pragma unroll
        for (int it = 0; it < 16; it++) {
            float v = h[(size_t)(n0 + it) * DIM + k];
            if (applyBN) {
                v = v * sc + sh;
                v = v > 0.f ? v : 0.02f * v;
            }
            sx[k * SXS + it] = v;
        }
    }
    __syncthreads();
    int j = tid;
    u64 accl[8], accr[8];
    u64 zz; PACK2(zz, 0.f, 0.f);
#pragma unroll
    for (int p = 0; p < 8; p++) { accl[p] = zz; accr[p] = zz; }
#pragma unroll 4
    for (int k = 0; k < 128; k++) {
        float wl = Wl[k * DIM + j];
        float wr = Wr[k * DIM + j];
        u64 wl2, wr2;
        PACK2(wl2, wl, wl);
        PACK2(wr2, wr, wr);
        const u64* xp = (const u64*)(sx + k * SXS);
#pragma unroll
        for (int p = 0; p < 8; p++) {
            u64 xv = xp[p];
            FMA2(accl[p], xv, wl2, accl[p]);
            FMA2(accr[p], xv, wr2, accr[p]);
        }
    }
    float blv = bl[j], brv = br[j];
#pragma unroll
    for (int p = 0; p < 8; p++) {
        float l0, l1, r0, r1;
        UNPK2(l0, l1, accl[p]);
        UNPK2(r0, r1, accr[p]);
        size_t b0 = (size_t)(n0 + 2 * p) * DIM + j;
        gl[b0] = l0 + blv;        gr[b0] = r0 + brv;
        gl[b0 + DIM] = l1 + blv;  gr[b0 + DIM] = r1 + brv;
    }
}

// ---------------- final projection (f32x2) ----------------
__global__ __launch_bounds__(128) void k_gemm_final(
    const float* __restrict__ h, const float* __restrict__ bnp,
    const float* __restrict__ Wf, const float* __restrict__ bf,
    float* __restrict__ out)
{
    __shared__ __align__(16) float sx[128 * SXS];
    __shared__ float sSc[DIM], sSh[DIM];
    int tid = threadIdx.x;
    sSc[tid] = bnp[tid];
    sSh[tid] = bnp[DIM + tid];
    __syncthreads();
    int n0 = blockIdx.x * 16;
    {
        int k = tid;
        float sc = sSc[k], sh = sSh[k];
#pragma unroll
        for (int it = 0; it < 16; it++) {
            float v = h[(size_t)(n0 + it) * DIM + k];
            v = v * sc + sh;
            v = v > 0.f ? v : 0.02f * v;
            sx[k * SXS + it] = v;
        }
    }
    __syncthreads();
    int j = tid;
    u64 acc[8];
    u64 zz; PACK2(zz, 0.f, 0.f);
#pragma unroll
    for (int p = 0; p < 8; p++) acc[p] = zz;
#pragma unroll 4
    for (int k = 0; k < 128; k++) {
        float wf = Wf[k * DIM + j];
        u64 wf2; PACK2(wf2, wf, wf);
        const u64* xp = (const u64*)(sx + k * SXS);
#pragma unroll
        for (int p = 0; p < 8; p++)
            FMA2(acc[p], xp[p], wf2, acc[p]);
    }
    float bfv = bf[j];
#pragma unroll
    for (int p = 0; p < 8; p++) {
        float o0, o1;
        UNPK2(o0, o1, acc[p]);
        size_t b0 = (size_t)(n0 + 2 * p) * DIM + j;
        out[b0] = o0 + bfv;
        out[b0 + DIM] = o1 + bfv;
    }
}

// ---------------- edge logits (edge-parallel, independent iterations) --------
// warp processes 80 consecutive edges; lane owns channels jb..jb+3 (head=lane>>3).
// w[e,h] = exp( att_h . leakyrelu_0.2( gl[src] + gr[dst] + EA[e] @ We ) )
__global__ __launch_bounds__(256) void k_logits(
    const int* __restrict__ ei, const float* __restrict__ gl,
    const float* __restrict__ gr, const float* __restrict__ We,
    const float* __restrict__ att, const float* __restrict__ EA,
    float* __restrict__ wbuf)
{
    int wid = blockIdx.x * 8 + (threadIdx.x >> 5);
    int lane = threadIdx.x & 31;
    int jb = lane * 4;

    u64 we01[16], we23[16];
#pragma unroll
    for (int kk = 0; kk < 16; kk++) {
        ulonglong2 wv = *(const ulonglong2*)(We + kk * DIM + jb);
        we01[kk] = wv.x; we23[kk] = wv.y;
    }
    float4 a4 = *(const float4*)(att + jb);

    int e0 = wid * EDGES_PER_WARP;
#pragma unroll 2
    for (int q = 0; q < EDGES_PER_WARP; q++) {
        int e = e0 + q;
        int src = ei[e];              // uniform across warp (broadcast)
        int dst = ei[N_EDGES + e];
        ulonglong2 glv = *(const ulonglong2*)(gl + (size_t)src * DIM + jb);
        ulonglong2 grv = *(const ulonglong2*)(gr + (size_t)dst * DIM + jb);
        u64 e01, e23;
        ADD2(e01, glv.x, grv.x);
        ADD2(e23, glv.y, grv.y);
        const float4* eap = (const float4*)(EA + (size_t)e * EDIM);
#pragma unroll
        for (int g = 0; g < 4; g++) {
            float4 eav = eap[g];      // uniform load, L1 broadcast
            u64 b0, b1, b2, b3;
            PACK2(b0, eav.x, eav.x);
            PACK2(b1, eav.y, eav.y);
            PACK2(b2, eav.z, eav.z);
            PACK2(b3, eav.w, eav.w);
            FMA2(e01, b0, we01[g * 4 + 0], e01);
            FMA2(e23, b0, we23[g * 4 + 0], e23);
            FMA2(e01, b1, we01[g * 4 + 1], e01);
            FMA2(e23, b1, we23[g * 4 + 1], e23);
            FMA2(e01, b2, we01[g * 4 + 2], e01);
            FMA2(e23, b2, we23[g * 4 + 2], e23);
            FMA2(e01, b3, we01[g * 4 + 3], e01);
            FMA2(e23, b3, we23[g * 4 + 3], e23);
        }
        float x0, x1, x2, x3;
        UNPK2(x0, x1, e01);
        UNPK2(x2, x3, e23);
        x0 = x0 > 0.f ? x0 : 0.2f * x0;
        x1 = x1 > 0.f ? x1 : 0.2f * x1;
        x2 = x2 > 0.f ? x2 : 0.2f * x2;
        x3 = x3 > 0.f ? x3 : 0.2f * x3;
        float t = x0 * a4.x;
        t = fmaf(x1, a4.y, t);
        t = fmaf(x2, a4.z, t);
        t = fmaf(x3, a4.w, t);
        t += __shfl_xor_sync(0xffffffffu, t, 1);
        t += __shfl_xor_sync(0xffffffffu, t, 2);
        t += __shfl_xor_sync(0xffffffffu, t, 4);
        float w = __expf(t);
        if ((lane & 7) == 0) wbuf[e * 4 + (lane >> 3)] = w;
    }
}

// ---------------- aggregation pass: warp per destination node ----------------
// den += w ; acc += w * gl[src] ; then normalize + bias + BN partials.
__global__ __launch_bounds__(256) void k_aggregate2(
    const int* __restrict__ off, const int2* __restrict__ einfo,
    const float* __restrict__ gl, const float* __restrict__ wbuf,
    const float* __restrict__ bias,
    float* __restrict__ hout, float* __restrict__ stats)
{
    __shared__ float sS[8 * DIM];
    __shared__ float sQ[8 * DIM];
    int tid = threadIdx.x;
    int lane = tid & 31;
    int wrp = tid >> 5;
    int n = blockIdx.x * 8 + wrp;
    int jb = lane * 4;
    int head = lane >> 3;

    float o0 = 0.f, o1 = 0.f, o2 = 0.f, o3 = 0.f;
    if (n < N_NODES) {
        u64 acc01, acc23;
        PACK2(acc01, 0.f, 0.f);
        acc23 = acc01;
        float den = 0.f;
        int beg = off[n], end = off[n + 1];
        for (int p = beg; p < end; p++) {
            int2 se = einfo[p];
            int s = se.x, eid = se.y;
            float4 w4 = *(const float4*)(wbuf + (size_t)eid * 4);  // uniform
            float w = (head == 0) ? w4.x : (head == 1) ? w4.y
                    : (head == 2) ? w4.z : w4.w;
            ulonglong2 glv = *(const ulonglong2*)(gl + (size_t)s * DIM + jb);
            den += w;
            u64 ww; PACK2(ww, w, w);
            FMA2(acc01, ww, glv.x, acc01);
            FMA2(acc23, ww, glv.y, acc23);
        }
        float rden = 1.0f / (den + 1e-16f);
        float a0, a1, a2, a3;
        UNPK2(a0, a1, acc01);
        UNPK2(a2, a3, acc23);
        o0 = a0 * rden + bias[jb + 0];
        o1 = a1 * rden + bias[jb + 1];
        o2 = a2 * rden + bias[jb + 2];
        o3 = a3 * rden + bias[jb + 3];
        *(float4*)(hout + (size_t)n * DIM + jb) = make_float4(o0, o1, o2, o3);
    }
    // BN partials: per-warp disjoint smem slices, no smem atomics
    int base = wrp * DIM + jb;
    sS[base + 0] = o0;  sQ[base + 0] = o0 * o0;
    sS[base + 1] = o1;  sQ[base + 1] = o1 * o1;
    sS[base + 2] = o2;  sQ[base + 2] = o2 * o2;
    sS[base + 3] = o3;  sQ[base + 3] = o3 * o3;
    __syncthreads();
    if (tid < DIM) {
        float s = 0.f, q = 0.f;
#pragma unroll
        for (int w = 0; w < 8; w++) {
            s += sS[w * DIM + tid];
            q += sQ[w * DIM + tid];
        }
        atomicAdd(&stats[tid], s);
        atomicAdd(&stats[DIM + tid], q);
    }
}

// ---------------- BN stats finalize (and reset accumulators) ----------------
__global__ void k_bn_finalize(float* __restrict__ stats,
                              const float* __restrict__ gamma,
                              const float* __restrict__ beta,
                              float* __restrict__ bnp)
{
    int j = threadIdx.x;
    float inv_n = 1.0f / (float)N_NODES;
    float mu = stats[j] * inv_n;
    float var = stats[DIM + j] * inv_n - mu * mu;
    float rs = rsqrtf(var + 1e-5f);
    float sc = rs * gamma[j];
    bnp[j] = sc;
    bnp[DIM + j] = beta[j] - mu * sc;
    stats[j] = 0.f;
    stats[DIM + j] = 0.f;
}

// ---------------- launch ----------------
extern "C" void kernel_launch(void* const* d_in, const int* in_sizes, int n_in,
                              void* d_out, int out_size)
{
    const float* x    = (const float*)d_in[0];
    const int*   ei   = (const int*)d_in[1];     // int32
    const float* ea   = (const float*)d_in[2];
    const float* Wl   = (const float*)d_in[3];
    const float* bl   = (const float*)d_in[4];
    const float* Wr   = (const float*)d_in[5];
    const float* br   = (const float*)d_in[6];
    const float* We   = (const float*)d_in[7];
    const float* att  = (const float*)d_in[8];
    const float* bias = (const float*)d_in[9];
    const float* gamma= (const float*)d_in[10];
    const float* beta = (const float*)d_in[11];
    const float* Wf   = (const float*)d_in[12];
    const float* bf   = (const float*)d_in[13];
    float* out = (float*)d_out;

    float *p_h, *p_gl, *p_gr, *p_w, *p_stats, *p_bnp;
    int *p_cnt, *p_off, *p_cur, *p_bsum;
    int2 *p_einfo;
    cudaGetSymbolAddress((void**)&p_h,     g_h);
    cudaGetSymbolAddress((void**)&p_gl,    g_gl);
    cudaGetSymbolAddress((void**)&p_gr,    g_gr);
    cudaGetSymbolAddress((void**)&p_w,     g_w);
    cudaGetSymbolAddress((void**)&p_stats, g_stats);
    cudaGetSymbolAddress((void**)&p_bnp,   g_bnp);
    cudaGetSymbolAddress((void**)&p_cnt,   g_cnt);
    cudaGetSymbolAddress((void**)&p_off,   g_off);
    cudaGetSymbolAddress((void**)&p_cur,   g_cursor);
    cudaGetSymbolAddress((void**)&p_bsum,  g_bsum);
    cudaGetSymbolAddress((void**)&p_einfo, g_einfo);

    int gemm_blocks = N_NODES / 16;          // 6250 (exact)
    int agg_blocks  = N_NODES / 8;           // 12500 (exact)

    // Layer 0 dense transforms first (independent of CSR), then CSR build
    // interleaved so the ncu-captured launch (#4) is the hot k_logits.
    k_gemm_dual<<<gemm_blocks, 128>>>(x, 0, p_bnp, Wl, bl, Wr, br, p_gl, p_gr);   // 1
    k_hist<<<(N_EDGES + 255) / 256, 256>>>(ei, p_cnt);                            // 2
    k_scan1<<<NBLK, 1024>>>(p_cnt, p_off, p_bsum);                                // 3
    k_logits<<<LOGIT_BLOCKS, 256>>>(ei, p_gl, p_gr, We, att, ea, p_w);            // 4 (profiled)
    k_scan23<<<(N_NODES + 255) / 256, 256>>>(p_off, p_bsum, p_cur);               // 5
    k_scatter<<<(N_EDGES + 255) / 256, 256>>>(ei, p_cur, p_einfo);                // 6

    for (int L = 0; L < 3; L++) {
        if (L > 0) {
            k_gemm_dual<<<gemm_blocks, 128>>>(p_h, 1, p_bnp,
                                              Wl + L * DIM * DIM, bl + L * DIM,
                                              Wr + L * DIM * DIM, br + L * DIM,
                                              p_gl, p_gr);
            k_logits<<<LOGIT_BLOCKS, 256>>>(ei, p_gl, p_gr, We + L * EDIM * DIM,
                                            att + L * DIM, ea, p_w);
        }
        k_aggregate2<<<agg_blocks, 256>>>(p_off, p_einfo, p_gl, p_w,
                                          bias + L * DIM, p_h, p_stats);
        k_bn_finalize<<<1, 128>>>(p_stats, gamma + L * DIM, beta + L * DIM, p_bnp);
    }
    k_gemm_final<<<gemm_blocks, 128>>>(p_h, p_bnp, Wf, bf, out);
}

// round 6
// speedup vs baseline: 1.2976x; 1.2976x over previous
#include <cuda_runtime.h>

#define N_NODES 100000
#define N_EDGES 1600000
#define DIM 128
#define EDIM 16
#define NBLK 98             // ceil(100000/1024)

typedef unsigned long long u64;

// f32x2 packed math (sm_103a; ptxas never auto-fuses these)
#define FMA2(d, a, b, c) asm("fma.rn.f32x2 %0, %1, %2, %3;" : "=l"(d) : "l"(a), "l"(b), "l"(c))
#define ADD2(d, a, b)    asm("add.rn.f32x2 %0, %1, %2;"     : "=l"(d) : "l"(a), "l"(b))
#define PACK2(d, lo, hi) asm("mov.b64 %0, {%1, %2};" : "=l"(d) : "r"(__float_as_uint(lo)), "r"(__float_as_uint(hi)))
#define UNPK2(lo, hi, v) do { unsigned _ulo, _uhi; asm("mov.b64 {%0, %1}, %2;" : "=r"(_ulo), "=r"(_uhi) : "l"(v)); lo = __uint_as_float(_ulo); hi = __uint_as_float(_uhi); } while (0)

// ---------------- static scratch (no allocations allowed) ----------------
__device__ __align__(16) float g_h[N_NODES * DIM];    // node features between layers
__device__ __align__(16) float g_gl[N_NODES * DIM];   // x @ Wl + bl
__device__ __align__(16) float g_gr[N_NODES * DIM];   // x @ Wr + br
__device__ __align__(16) u64   g_ea2[(size_t)N_EDGES * EDIM]; // EA duplicated (lo=hi)
__device__ int   g_cnt[N_NODES];                      // zero at load; re-zeroed by scan1
__device__ int   g_off[N_NODES + 1];
__device__ int   g_cursor[N_NODES];
__device__ int   g_bsum[128];
__device__ __align__(16) int2 g_einfo[N_EDGES];       // (src, edge_id) sorted by dst
__device__ float g_stats[2 * DIM];                    // sum | sumsq (re-zeroed by bn_finalize)
__device__ float g_bnp[2 * DIM];                      // scale | shift

// ---------------- fused histogram + edge-attr duplication prep --------------
// edge_index is INT32 (JAX x64-disabled downcast)
__global__ __launch_bounds__(256) void k_histprep(
    const int* __restrict__ ei, int* __restrict__ cnt,
    const float* __restrict__ EA, u64* __restrict__ ea2)
{
    __shared__ float sea[256 * EDIM];
    int e = blockIdx.x * 256 + threadIdx.x;
    atomicAdd(&cnt[ei[N_EDGES + e]], 1);
    size_t base = (size_t)blockIdx.x * 256 * EDIM;
#pragma unroll
    for (int i = 0; i < EDIM; i++) {
        int idx = threadIdx.x + i * 256;
        sea[idx] = EA[base + idx];          // coalesced
    }
    __syncthreads();
#pragma unroll
    for (int i = 0; i < EDIM; i++) {
        int idx = threadIdx.x + i * 256;
        float v = sea[idx];
        u64 d; PACK2(d, v, v);
        ea2[base + idx] = d;                // coalesced (row-major [E][16] preserved)
    }
}

__global__ void k_scan1(int* __restrict__ cnt, int* __restrict__ off,
                        int* __restrict__ bsum) {
    __shared__ int s[1024];
    int tid = threadIdx.x;
    int i = blockIdx.x * 1024 + tid;
    int v = (i < N_NODES) ? cnt[i] : 0;
    if (i < N_NODES) cnt[i] = 0;           // re-zero for next call
    s[tid] = v; __syncthreads();
    for (int d = 1; d < 1024; d <<= 1) {
        int t = (tid >= d) ? s[tid - d] : 0;
        __syncthreads();
        s[tid] += t;
        __syncthreads();
    }
    if (i < N_NODES) off[i] = s[tid] - v;   // exclusive within block
    if (tid == 1023) bsum[blockIdx.x] = s[1023];
}

__global__ void k_scan23(int* __restrict__ off, const int* __restrict__ bsum,
                         int* __restrict__ cursor) {
    __shared__ int sp[NBLK];
    int tid = threadIdx.x;
    if (tid == 0) {
        int acc = 0;
        for (int b = 0; b < NBLK; b++) { sp[b] = acc; acc += bsum[b]; }
    }
    __syncthreads();
    int i = blockIdx.x * blockDim.x + tid;
    if (i < N_NODES) {
        int o = off[i] + sp[i >> 10];
        off[i] = o;
        cursor[i] = o;
    }
    if (i == 0) off[N_NODES] = N_EDGES;
}

__global__ void k_scatter(const int* __restrict__ ei, int* __restrict__ cursor,
                          int2* __restrict__ einfo) {
    int e = blockIdx.x * blockDim.x + threadIdx.x;
    if (e < N_EDGES) {
        int src = ei[e];
        int dst = ei[N_EDGES + e];
        int pos = atomicAdd(&cursor[dst], 1);
        einfo[pos] = make_int2(src, e);
    }
}

// ---------------- dual node GEMM (f32x2): gl = f(h)@Wl+bl, gr = f(h)@Wr+br ----
#define SXS 20
__global__ __launch_bounds__(128) void k_gemm_dual(
    const float* __restrict__ h, int applyBN, const float* __restrict__ bnp,
    const float* __restrict__ Wl, const float* __restrict__ bl,
    const float* __restrict__ Wr, const float* __restrict__ br,
    float* __restrict__ gl, float* __restrict__ gr)
{
    __shared__ __align__(16) float sx[128 * SXS];
    __shared__ float sSc[DIM], sSh[DIM];
    int tid = threadIdx.x;
    sSc[tid] = bnp[tid];
    sSh[tid] = bnp[DIM + tid];
    __syncthreads();
    int n0 = blockIdx.x * 16;
    {
        int k = tid;
        float sc = sSc[k], sh = sSh[k];
#pragma unroll
        for (int it = 0; it < 16; it++) {
            float v = h[(size_t)(n0 + it) * DIM + k];
            if (applyBN) {
                v = v * sc + sh;
                v = v > 0.f ? v : 0.02f * v;
            }
            sx[k * SXS + it] = v;
        }
    }
    __syncthreads();
    int j = tid;
    u64 accl[8], accr[8];
    u64 zz; PACK2(zz, 0.f, 0.f);
#pragma unroll
    for (int p = 0; p < 8; p++) { accl[p] = zz; accr[p] = zz; }
#pragma unroll 4
    for (int k = 0; k < 128; k++) {
        float wl = Wl[k * DIM + j];
        float wr = Wr[k * DIM + j];
        u64 wl2, wr2;
        PACK2(wl2, wl, wl);
        PACK2(wr2, wr, wr);
        const u64* xp = (const u64*)(sx + k * SXS);
#pragma unroll
        for (int p = 0; p < 8; p++) {
            u64 xv = xp[p];
            FMA2(accl[p], xv, wl2, accl[p]);
            FMA2(accr[p], xv, wr2, accr[p]);
        }
    }
    float blv = bl[j], brv = br[j];
#pragma unroll
    for (int p = 0; p < 8; p++) {
        float l0, l1, r0, r1;
        UNPK2(l0, l1, accl[p]);
        UNPK2(r0, r1, accr[p]);
        size_t b0 = (size_t)(n0 + 2 * p) * DIM + j;
        gl[b0] = l0 + blv;        gr[b0] = r0 + brv;
        gl[b0 + DIM] = l1 + blv;  gr[b0 + DIM] = r1 + brv;
    }
}

// ---------------- final projection (f32x2) ----------------
__global__ __launch_bounds__(128) void k_gemm_final(
    const float* __restrict__ h, const float* __restrict__ bnp,
    const float* __restrict__ Wf, const float* __restrict__ bf,
    float* __restrict__ out)
{
    __shared__ __align__(16) float sx[128 * SXS];
    __shared__ float sSc[DIM], sSh[DIM];
    int tid = threadIdx.x;
    sSc[tid] = bnp[tid];
    sSh[tid] = bnp[DIM + tid];
    __syncthreads();
    int n0 = blockIdx.x * 16;
    {
        int k = tid;
        float sc = sSc[k], sh = sSh[k];
#pragma unroll
        for (int it = 0; it < 16; it++) {
            float v = h[(size_t)(n0 + it) * DIM + k];
            v = v * sc + sh;
            v = v > 0.f ? v : 0.02f * v;
            sx[k * SXS + it] = v;
        }
    }
    __syncthreads();
    int j = tid;
    u64 acc[8];
    u64 zz; PACK2(zz, 0.f, 0.f);
#pragma unroll
    for (int p = 0; p < 8; p++) acc[p] = zz;
#pragma unroll 4
    for (int k = 0; k < 128; k++) {
        float wf = Wf[k * DIM + j];
        u64 wf2; PACK2(wf2, wf, wf);
        const u64* xp = (const u64*)(sx + k * SXS);
#pragma unroll
        for (int p = 0; p < 8; p++)
            FMA2(acc[p], xp[p], wf2, acc[p]);
    }
    float bfv = bf[j];
#pragma unroll
    for (int p = 0; p < 8; p++) {
        float o0, o1;
        UNPK2(o0, o1, acc[p]);
        size_t b0 = (size_t)(n0 + 2 * p) * DIM + j;
        out[b0] = o0 + bfv;
        out[b0 + DIM] = o1 + bfv;
    }
}

// ---------------- fused GATv2 aggregation: one warp per destination node -----
// Lane owns channels jb..jb+3 (jb = lane*4; head = lane>>3).
// Per edge: transform (32 FMA2, EA pre-duplicated), lrelu, head-dot, exp,
// weighted accumulate. 2-edge manual unroll for ILP.
__device__ __forceinline__ void edge_work(
    int2 se, const u64* __restrict__ ea2, const float* __restrict__ gl, int jb,
    const u64* we01, const u64* we23, u64 gr01, u64 gr23, float4 a4,
    u64& acc01, u64& acc23, float& den)
{
    ulonglong2 glv = *(const ulonglong2*)(gl + (size_t)se.x * DIM + jb);
    u64 e01, e23;
    ADD2(e01, glv.x, gr01);
    ADD2(e23, glv.y, gr23);
    const ulonglong2* ep = (const ulonglong2*)(ea2 + (size_t)se.y * EDIM);
#pragma unroll
    for (int g = 0; g < 8; g++) {
        ulonglong2 bb = ep[g];              // uniform 16B load, L1 broadcast
        FMA2(e01, bb.x, we01[2 * g],     e01);
        FMA2(e23, bb.x, we23[2 * g],     e23);
        FMA2(e01, bb.y, we01[2 * g + 1], e01);
        FMA2(e23, bb.y, we23[2 * g + 1], e23);
    }
    float x0, x1, x2, x3;
    UNPK2(x0, x1, e01);
    UNPK2(x2, x3, e23);
    x0 = x0 > 0.f ? x0 : 0.2f * x0;         // GATv2 leaky relu 0.2
    x1 = x1 > 0.f ? x1 : 0.2f * x1;
    x2 = x2 > 0.f ? x2 : 0.2f * x2;
    x3 = x3 > 0.f ? x3 : 0.2f * x3;
    float t = x0 * a4.x;
    t = fmaf(x1, a4.y, t);
    t = fmaf(x2, a4.z, t);
    t = fmaf(x3, a4.w, t);
    t += __shfl_xor_sync(0xffffffffu, t, 1);
    t += __shfl_xor_sync(0xffffffffu, t, 2);
    t += __shfl_xor_sync(0xffffffffu, t, 4);
    float w = __expf(t);
    den += w;
    u64 ww; PACK2(ww, w, w);
    FMA2(acc01, ww, glv.x, acc01);
    FMA2(acc23, ww, glv.y, acc23);
}

__global__ __launch_bounds__(256) void k_aggregate(
    const int* __restrict__ off, const int2* __restrict__ einfo,
    const u64* __restrict__ ea2,
    const float* __restrict__ gl, const float* __restrict__ gr,
    const float* __restrict__ We, const float* __restrict__ att,
    const float* __restrict__ bias,
    float* __restrict__ hout, float* __restrict__ stats)
{
    __shared__ float sS[8 * DIM];
    __shared__ float sQ[8 * DIM];
    int tid = threadIdx.x;
    int lane = tid & 31;
    int wrp = tid >> 5;
    int n = blockIdx.x * 8 + wrp;
    int jb = lane * 4;

    u64 we01[16], we23[16];
#pragma unroll
    for (int kk = 0; kk < 16; kk++) {
        ulonglong2 wv = *(const ulonglong2*)(We + kk * DIM + jb);
        we01[kk] = wv.x; we23[kk] = wv.y;
    }
    float4 a4 = *(const float4*)(att + jb);
    float4 b4 = *(const float4*)(bias + jb);

    float o0 = 0.f, o1 = 0.f, o2 = 0.f, o3 = 0.f;
    if (n < N_NODES) {
        ulonglong2 grv = *(const ulonglong2*)(gr + (size_t)n * DIM + jb);
        u64 gr01 = grv.x, gr23 = grv.y;
        u64 acc01, acc23;
        PACK2(acc01, 0.f, 0.f);
        acc23 = acc01;
        float den = 0.f;
        int beg = off[n], end = off[n + 1];
        int p = beg;
#pragma unroll 1
        for (; p + 1 < end; p += 2) {
            int2 sa = einfo[p];
            int2 sb = einfo[p + 1];
            edge_work(sa, ea2, gl, jb, we01, we23, gr01, gr23, a4, acc01, acc23, den);
            edge_work(sb, ea2, gl, jb, we01, we23, gr01, gr23, a4, acc01, acc23, den);
        }
        if (p < end)
            edge_work(einfo[p], ea2, gl, jb, we01, we23, gr01, gr23, a4, acc01, acc23, den);

        float rden = 1.0f / (den + 1e-16f);
        float a0, a1, a2, a3;
        UNPK2(a0, a1, acc01);
        UNPK2(a2, a3, acc23);
        o0 = a0 * rden + b4.x;
        o1 = a1 * rden + b4.y;
        o2 = a2 * rden + b4.z;
        o3 = a3 * rden + b4.w;
        *(float4*)(hout + (size_t)n * DIM + jb) = make_float4(o0, o1, o2, o3);
    }
    // BN partials: per-warp disjoint smem slices, no smem atomics
    int base = wrp * DIM + jb;
    sS[base + 0] = o0;  sQ[base + 0] = o0 * o0;
    sS[base + 1] = o1;  sQ[base + 1] = o1 * o1;
    sS[base + 2] = o2;  sQ[base + 2] = o2 * o2;
    sS[base + 3] = o3;  sQ[base + 3] = o3 * o3;
    __syncthreads();
    if (tid < DIM) {
        float s = 0.f, q = 0.f;
#pragma unroll
        for (int w = 0; w < 8; w++) {
            s += sS[w * DIM + tid];
            q += sQ[w * DIM + tid];
        }
        atomicAdd(&stats[tid], s);
        atomicAdd(&stats[DIM + tid], q);
    }
}

// ---------------- BN stats finalize (and reset accumulators) ----------------
__global__ void k_bn_finalize(float* __restrict__ stats,
                              const float* __restrict__ gamma,
                              const float* __restrict__ beta,
                              float* __restrict__ bnp)
{
    int j = threadIdx.x;
    float inv_n = 1.0f / (float)N_NODES;
    float mu = stats[j] * inv_n;
    float var = stats[DIM + j] * inv_n - mu * mu;
    float rs = rsqrtf(var + 1e-5f);
    float sc = rs * gamma[j];
    bnp[j] = sc;
    bnp[DIM + j] = beta[j] - mu * sc;
    stats[j] = 0.f;
    stats[DIM + j] = 0.f;
}

// ---------------- launch ----------------
extern "C" void kernel_launch(void* const* d_in, const int* in_sizes, int n_in,
                              void* d_out, int out_size)
{
    const float* x    = (const float*)d_in[0];
    const int*   ei   = (const int*)d_in[1];     // int32
    const float* ea   = (const float*)d_in[2];
    const float* Wl   = (const float*)d_in[3];
    const float* bl   = (const float*)d_in[4];
    const float* Wr   = (const float*)d_in[5];
    const float* br   = (const float*)d_in[6];
    const float* We   = (const float*)d_in[7];
    const float* att  = (const float*)d_in[8];
    const float* bias = (const float*)d_in[9];
    const float* gamma= (const float*)d_in[10];
    const float* beta = (const float*)d_in[11];
    const float* Wf   = (const float*)d_in[12];
    const float* bf   = (const float*)d_in[13];
    float* out = (float*)d_out;

    float *p_h, *p_gl, *p_gr, *p_stats, *p_bnp;
    u64 *p_ea2;
    int *p_cnt, *p_off, *p_cur, *p_bsum;
    int2 *p_einfo;
    cudaGetSymbolAddress((void**)&p_h,     g_h);
    cudaGetSymbolAddress((void**)&p_gl,    g_gl);
    cudaGetSymbolAddress((void**)&p_gr,    g_gr);
    cudaGetSymbolAddress((void**)&p_ea2,   g_ea2);
    cudaGetSymbolAddress((void**)&p_stats, g_stats);
    cudaGetSymbolAddress((void**)&p_bnp,   g_bnp);
    cudaGetSymbolAddress((void**)&p_cnt,   g_cnt);
    cudaGetSymbolAddress((void**)&p_off,   g_off);
    cudaGetSymbolAddress((void**)&p_cur,   g_cursor);
    cudaGetSymbolAddress((void**)&p_bsum,  g_bsum);
    cudaGetSymbolAddress((void**)&p_einfo, g_einfo);

    int gemm_blocks = N_NODES / 16;          // 6250 (exact)
    int agg_blocks  = N_NODES / 8;           // 12500 (exact)

    // launch #4 = k_gemm_dual (ncu capture slot)
    k_histprep<<<N_EDGES / 256, 256>>>(ei, p_cnt, ea, p_ea2);            // 1
    k_scan1<<<NBLK, 1024>>>(p_cnt, p_off, p_bsum);                       // 2
    k_scan23<<<(N_NODES + 255) / 256, 256>>>(p_off, p_bsum, p_cur);      // 3
    k_gemm_dual<<<gemm_blocks, 128>>>(x, 0, p_bnp, Wl, bl, Wr, br,
                                      p_gl, p_gr);                       // 4 (profiled)
    k_scatter<<<(N_EDGES + 255) / 256, 256>>>(ei, p_cur, p_einfo);       // 5

    for (int L = 0; L < 3; L++) {
        if (L > 0) {
            k_gemm_dual<<<gemm_blocks, 128>>>(p_h, 1, p_bnp,
                                              Wl + L * DIM * DIM, bl + L * DIM,
                                              Wr + L * DIM * DIM, br + L * DIM,
                                              p_gl, p_gr);
        }
        k_aggregate<<<agg_blocks, 256>>>(p_off, p_einfo, p_ea2, p_gl, p_gr,
                                         We + L * EDIM * DIM, att + L * DIM,
                                         bias + L * DIM, p_h, p_stats);
        k_bn_finalize<<<1, 128>>>(p_stats, gamma + L * DIM, beta + L * DIM, p_bnp);
    }
    k_gemm_final<<<gemm_blocks, 128>>>(p_h, p_bnp, Wf, bf, out);
}

// round 7
// speedup vs baseline: 1.5208x; 1.1719x over previous
#include <cuda_runtime.h>

#define N_NODES 100000
#define N_EDGES 1600000
#define DIM 128
#define EDIM 16
#define NBLK 98             // ceil(100000/1024)

typedef unsigned long long u64;

// f32x2 packed math (sm_103a; ptxas never auto-fuses these)
#define FMA2(d, a, b, c) asm("fma.rn.f32x2 %0, %1, %2, %3;" : "=l"(d) : "l"(a), "l"(b), "l"(c))
#define ADD2(d, a, b)    asm("add.rn.f32x2 %0, %1, %2;"     : "=l"(d) : "l"(a), "l"(b))
#define PACK2(d, lo, hi) asm("mov.b64 %0, {%1, %2};" : "=l"(d) : "r"(__float_as_uint(lo)), "r"(__float_as_uint(hi)))
#define UNPK2(lo, hi, v) do { unsigned _ulo, _uhi; asm("mov.b64 {%0, %1}, %2;" : "=r"(_ulo), "=r"(_uhi) : "l"(v)); lo = __uint_as_float(_ulo); hi = __uint_as_float(_uhi); } while (0)

// ---------------- static scratch (no allocations allowed) ----------------
__device__ __align__(16) float g_h[N_NODES * DIM];    // node features between layers
__device__ __align__(16) float g_gl[N_NODES * DIM];   // x @ Wl + bl
__device__ __align__(16) float g_gr[N_NODES * DIM];   // x @ Wr + br
__device__ __align__(16) float g_ee[(size_t)N_EDGES * DIM]; // EA @ We per edge (819MB)
__device__ int   g_cnt[N_NODES];                      // zero at load; re-zeroed by scan1
__device__ int   g_off[N_NODES + 1];
__device__ int   g_cursor[N_NODES];
__device__ int   g_bsum[128];
__device__ __align__(16) int2 g_einfo[N_EDGES];       // (src, edge_id) sorted by dst
__device__ float g_stats[2 * DIM];                    // sum | sumsq (re-zeroed by bn_finalize)
__device__ float g_bnp[2 * DIM];                      // scale | shift

// ---------------- CSR build ----------------
// edge_index is INT32 (JAX x64-disabled downcast)
__global__ void k_hist(const int* __restrict__ ei, int* __restrict__ cnt) {
    int e = blockIdx.x * blockDim.x + threadIdx.x;
    if (e < N_EDGES) atomicAdd(&cnt[ei[N_EDGES + e]], 1);
}

__global__ void k_scan1(int* __restrict__ cnt, int* __restrict__ off,
                        int* __restrict__ bsum) {
    __shared__ int s[1024];
    int tid = threadIdx.x;
    int i = blockIdx.x * 1024 + tid;
    int v = (i < N_NODES) ? cnt[i] : 0;
    if (i < N_NODES) cnt[i] = 0;           // re-zero for next call
    s[tid] = v; __syncthreads();
    for (int d = 1; d < 1024; d <<= 1) {
        int t = (tid >= d) ? s[tid - d] : 0;
        __syncthreads();
        s[tid] += t;
        __syncthreads();
    }
    if (i < N_NODES) off[i] = s[tid] - v;   // exclusive within block
    if (tid == 1023) bsum[blockIdx.x] = s[1023];
}

__global__ void k_scan23(int* __restrict__ off, const int* __restrict__ bsum,
                         int* __restrict__ cursor) {
    __shared__ int sp[NBLK];
    int tid = threadIdx.x;
    if (tid == 0) {
        int acc = 0;
        for (int b = 0; b < NBLK; b++) { sp[b] = acc; acc += bsum[b]; }
    }
    __syncthreads();
    int i = blockIdx.x * blockDim.x + tid;
    if (i < N_NODES) {
        int o = off[i] + sp[i >> 10];
        off[i] = o;
        cursor[i] = o;
    }
    if (i == 0) off[N_NODES] = N_EDGES;
}

__global__ void k_scatter(const int* __restrict__ ei, int* __restrict__ cursor,
                          int2* __restrict__ einfo) {
    int e = blockIdx.x * blockDim.x + threadIdx.x;
    if (e < N_EDGES) {
        int src = ei[e];
        int dst = ei[N_EDGES + e];
        int pos = atomicAdd(&cursor[dst], 1);
        einfo[pos] = make_int2(src, e);
    }
}

// ---------------- edge transform GEMM: ee[e] = EA[e] @ We --------------------
// Warp handles 32 consecutive edges; lane owns channels jb..jb+3. We in regs.
// Pure streaming compute: independent iterations, deep MLP, no shfl/exp.
__global__ __launch_bounds__(256) void k_ee(
    const float* __restrict__ EA, const float* __restrict__ We,
    float* __restrict__ ee)
{
    int wid = blockIdx.x * 8 + (threadIdx.x >> 5);
    int lane = threadIdx.x & 31;
    int jb = lane * 4;

    u64 we01[16], we23[16];
#pragma unroll
    for (int kk = 0; kk < 16; kk++) {
        ulonglong2 wv = *(const ulonglong2*)(We + kk * DIM + jb);
        we01[kk] = wv.x; we23[kk] = wv.y;
    }

    int e0 = wid * 32;
#pragma unroll 2
    for (int q = 0; q < 32; q++) {
        int e = e0 + q;
        const float4* eap = (const float4*)(EA + (size_t)e * EDIM);
        u64 e01, e23;
        PACK2(e01, 0.f, 0.f);
        e23 = e01;
#pragma unroll
        for (int g = 0; g < 4; g++) {
            float4 eav = eap[g];            // uniform load, L1 broadcast
            u64 b0, b1, b2, b3;
            PACK2(b0, eav.x, eav.x);
            PACK2(b1, eav.y, eav.y);
            PACK2(b2, eav.z, eav.z);
            PACK2(b3, eav.w, eav.w);
            FMA2(e01, b0, we01[g * 4 + 0], e01);
            FMA2(e23, b0, we23[g * 4 + 0], e23);
            FMA2(e01, b1, we01[g * 4 + 1], e01);
            FMA2(e23, b1, we23[g * 4 + 1], e23);
            FMA2(e01, b2, we01[g * 4 + 2], e01);
            FMA2(e23, b2, we23[g * 4 + 2], e23);
            FMA2(e01, b3, we01[g * 4 + 3], e01);
            FMA2(e23, b3, we23[g * 4 + 3], e23);
        }
        ulonglong2 o; o.x = e01; o.y = e23;
        *(ulonglong2*)(ee + (size_t)e * DIM + jb) = o;   // 512B coalesced per warp
    }
}

// ---------------- dual node GEMM (f32x2): gl = f(h)@Wl+bl, gr = f(h)@Wr+br ----
#define SXS 20
__global__ __launch_bounds__(128) void k_gemm_dual(
    const float* __restrict__ h, int applyBN, const float* __restrict__ bnp,
    const float* __restrict__ Wl, const float* __restrict__ bl,
    const float* __restrict__ Wr, const float* __restrict__ br,
    float* __restrict__ gl, float* __restrict__ gr)
{
    __shared__ __align__(16) float sx[128 * SXS];
    __shared__ float sSc[DIM], sSh[DIM];
    int tid = threadIdx.x;
    sSc[tid] = bnp[tid];
    sSh[tid] = bnp[DIM + tid];
    __syncthreads();
    int n0 = blockIdx.x * 16;
    {
        int k = tid;
        float sc = sSc[k], sh = sSh[k];
#pragma unroll
        for (int it = 0; it < 16; it++) {
            float v = h[(size_t)(n0 + it) * DIM + k];
            if (applyBN) {
                v = v * sc + sh;
                v = v > 0.f ? v : 0.02f * v;
            }
            sx[k * SXS + it] = v;
        }
    }
    __syncthreads();
    int j = tid;
    u64 accl[8], accr[8];
    u64 zz; PACK2(zz, 0.f, 0.f);
#pragma unroll
    for (int p = 0; p < 8; p++) { accl[p] = zz; accr[p] = zz; }
#pragma unroll 4
    for (int k = 0; k < 128; k++) {
        float wl = Wl[k * DIM + j];
        float wr = Wr[k * DIM + j];
        u64 wl2, wr2;
        PACK2(wl2, wl, wl);
        PACK2(wr2, wr, wr);
        const ulonglong2* xp2 = (const ulonglong2*)(sx + k * SXS);
#pragma unroll
        for (int p = 0; p < 4; p++) {
            ulonglong2 xv = xp2[p];         // LDS.128
            FMA2(accl[2 * p],     xv.x, wl2, accl[2 * p]);
            FMA2(accr[2 * p],     xv.x, wr2, accr[2 * p]);
            FMA2(accl[2 * p + 1], xv.y, wl2, accl[2 * p + 1]);
            FMA2(accr[2 * p + 1], xv.y, wr2, accr[2 * p + 1]);
        }
    }
    float blv = bl[j], brv = br[j];
#pragma unroll
    for (int p = 0; p < 8; p++) {
        float l0, l1, r0, r1;
        UNPK2(l0, l1, accl[p]);
        UNPK2(r0, r1, accr[p]);
        size_t b0 = (size_t)(n0 + 2 * p) * DIM + j;
        gl[b0] = l0 + blv;        gr[b0] = r0 + brv;
        gl[b0 + DIM] = l1 + blv;  gr[b0 + DIM] = r1 + brv;
    }
}

// ---------------- final projection (f32x2) ----------------
__global__ __launch_bounds__(128) void k_gemm_final(
    const float* __restrict__ h, const float* __restrict__ bnp,
    const float* __restrict__ Wf, const float* __restrict__ bf,
    float* __restrict__ out)
{
    __shared__ __align__(16) float sx[128 * SXS];
    __shared__ float sSc[DIM], sSh[DIM];
    int tid = threadIdx.x;
    sSc[tid] = bnp[tid];
    sSh[tid] = bnp[DIM + tid];
    __syncthreads();
    int n0 = blockIdx.x * 16;
    {
        int k = tid;
        float sc = sSc[k], sh = sSh[k];
#pragma unroll
        for (int it = 0; it < 16; it++) {
            float v = h[(size_t)(n0 + it) * DIM + k];
            v = v * sc + sh;
            v = v > 0.f ? v : 0.02f * v;
            sx[k * SXS + it] = v;
        }
    }
    __syncthreads();
    int j = tid;
    u64 acc[8];
    u64 zz; PACK2(zz, 0.f, 0.f);
#pragma unroll
    for (int p = 0; p < 8; p++) acc[p] = zz;
#pragma unroll 4
    for (int k = 0; k < 128; k++) {
        float wf = Wf[k * DIM + j];
        u64 wf2; PACK2(wf2, wf, wf);
        const ulonglong2* xp2 = (const ulonglong2*)(sx + k * SXS);
#pragma unroll
        for (int p = 0; p < 4; p++) {
            ulonglong2 xv = xp2[p];
            FMA2(acc[2 * p],     xv.x, wf2, acc[2 * p]);
            FMA2(acc[2 * p + 1], xv.y, wf2, acc[2 * p + 1]);
        }
    }
    float bfv = bf[j];
#pragma unroll
    for (int p = 0; p < 8; p++) {
        float o0, o1;
        UNPK2(o0, o1, acc[p]);
        size_t b0 = (size_t)(n0 + 2 * p) * DIM + j;
        out[b0] = o0 + bfv;
        out[b0 + DIM] = o1 + bfv;
    }
}

// ---------------- GATv2 aggregation: one warp per destination node -----------
// Slim loop (~30 instr/edge, low regs): e = gl[src]+gr[n]+ee[eid]; lrelu; dot;
// head-reduce; exp; weighted accumulate.
__global__ __launch_bounds__(256) void k_aggregate(
    const int* __restrict__ off, const int2* __restrict__ einfo,
    const float* __restrict__ ee,
    const float* __restrict__ gl, const float* __restrict__ gr,
    const float* __restrict__ att, const float* __restrict__ bias,
    float* __restrict__ hout, float* __restrict__ stats)
{
    __shared__ float sS[8 * DIM];
    __shared__ float sQ[8 * DIM];
    int tid = threadIdx.x;
    int lane = tid & 31;
    int wrp = tid >> 5;
    int n = blockIdx.x * 8 + wrp;
    int jb = lane * 4;

    float4 a4 = *(const float4*)(att + jb);
    float4 b4 = *(const float4*)(bias + jb);

    float o0 = 0.f, o1 = 0.f, o2 = 0.f, o3 = 0.f;
    if (n < N_NODES) {
        ulonglong2 grv = *(const ulonglong2*)(gr + (size_t)n * DIM + jb);
        u64 gr01 = grv.x, gr23 = grv.y;
        u64 acc01, acc23;
        PACK2(acc01, 0.f, 0.f);
        acc23 = acc01;
        float den = 0.f;
        int beg = off[n], end = off[n + 1];
#pragma unroll 2
        for (int p = beg; p < end; p++) {
            int2 se = einfo[p];
            ulonglong2 eev = *(const ulonglong2*)(ee + (size_t)se.y * DIM + jb);
            ulonglong2 glv = *(const ulonglong2*)(gl + (size_t)se.x * DIM + jb);
            u64 e01, e23;
            ADD2(e01, glv.x, gr01);
            ADD2(e23, glv.y, gr23);
            ADD2(e01, e01, eev.x);
            ADD2(e23, e23, eev.y);
            float x0, x1, x2, x3;
            UNPK2(x0, x1, e01);
            UNPK2(x2, x3, e23);
            x0 = x0 > 0.f ? x0 : 0.2f * x0;     // GATv2 leaky relu 0.2
            x1 = x1 > 0.f ? x1 : 0.2f * x1;
            x2 = x2 > 0.f ? x2 : 0.2f * x2;
            x3 = x3 > 0.f ? x3 : 0.2f * x3;
            float t = x0 * a4.x;
            t = fmaf(x1, a4.y, t);
            t = fmaf(x2, a4.z, t);
            t = fmaf(x3, a4.w, t);
            t += __shfl_xor_sync(0xffffffffu, t, 1);
            t += __shfl_xor_sync(0xffffffffu, t, 2);
            t += __shfl_xor_sync(0xffffffffu, t, 4);
            float w = __expf(t);
            den += w;
            u64 ww; PACK2(ww, w, w);
            FMA2(acc01, ww, glv.x, acc01);
            FMA2(acc23, ww, glv.y, acc23);
        }
        float rden = 1.0f / (den + 1e-16f);
        float a0, a1, a2, a3;
        UNPK2(a0, a1, acc01);
        UNPK2(a2, a3, acc23);
        o0 = a0 * rden + b4.x;
        o1 = a1 * rden + b4.y;
        o2 = a2 * rden + b4.z;
        o3 = a3 * rden + b4.w;
        *(float4*)(hout + (size_t)n * DIM + jb) = make_float4(o0, o1, o2, o3);
    }
    // BN partials: per-warp disjoint smem slices, no smem atomics
    int base = wrp * DIM + jb;
    sS[base + 0] = o0;  sQ[base + 0] = o0 * o0;
    sS[base + 1] = o1;  sQ[base + 1] = o1 * o1;
    sS[base + 2] = o2;  sQ[base + 2] = o2 * o2;
    sS[base + 3] = o3;  sQ[base + 3] = o3 * o3;
    __syncthreads();
    if (tid < DIM) {
        float s = 0.f, q = 0.f;
#pragma unroll
        for (int w = 0; w < 8; w++) {
            s += sS[w * DIM + tid];
            q += sQ[w * DIM + tid];
        }
        atomicAdd(&stats[tid], s);
        atomicAdd(&stats[DIM + tid], q);
    }
}

// ---------------- BN stats finalize (and reset accumulators) ----------------
__global__ void k_bn_finalize(float* __restrict__ stats,
                              const float* __restrict__ gamma,
                              const float* __restrict__ beta,
                              float* __restrict__ bnp)
{
    int j = threadIdx.x;
    float inv_n = 1.0f / (float)N_NODES;
    float mu = stats[j] * inv_n;
    float var = stats[DIM + j] * inv_n - mu * mu;
    float rs = rsqrtf(var + 1e-5f);
    float sc = rs * gamma[j];
    bnp[j] = sc;
    bnp[DIM + j] = beta[j] - mu * sc;
    stats[j] = 0.f;
    stats[DIM + j] = 0.f;
}

// ---------------- launch ----------------
extern "C" void kernel_launch(void* const* d_in, const int* in_sizes, int n_in,
                              void* d_out, int out_size)
{
    const float* x    = (const float*)d_in[0];
    const int*   ei   = (const int*)d_in[1];     // int32
    const float* ea   = (const float*)d_in[2];
    const float* Wl   = (const float*)d_in[3];
    const float* bl   = (const float*)d_in[4];
    const float* Wr   = (const float*)d_in[5];
    const float* br   = (const float*)d_in[6];
    const float* We   = (const float*)d_in[7];
    const float* att  = (const float*)d_in[8];
    const float* bias = (const float*)d_in[9];
    const float* gamma= (const float*)d_in[10];
    const float* beta = (const float*)d_in[11];
    const float* Wf   = (const float*)d_in[12];
    const float* bf   = (const float*)d_in[13];
    float* out = (float*)d_out;

    float *p_h, *p_gl, *p_gr, *p_ee, *p_stats, *p_bnp;
    int *p_cnt, *p_off, *p_cur, *p_bsum;
    int2 *p_einfo;
    cudaGetSymbolAddress((void**)&p_h,     g_h);
    cudaGetSymbolAddress((void**)&p_gl,    g_gl);
    cudaGetSymbolAddress((void**)&p_gr,    g_gr);
    cudaGetSymbolAddress((void**)&p_ee,    g_ee);
    cudaGetSymbolAddress((void**)&p_stats, g_stats);
    cudaGetSymbolAddress((void**)&p_bnp,   g_bnp);
    cudaGetSymbolAddress((void**)&p_cnt,   g_cnt);
    cudaGetSymbolAddress((void**)&p_off,   g_off);
    cudaGetSymbolAddress((void**)&p_cur,   g_cursor);
    cudaGetSymbolAddress((void**)&p_bsum,  g_bsum);
    cudaGetSymbolAddress((void**)&p_einfo, g_einfo);

    int gemm_blocks = N_NODES / 16;          // 6250 (exact)
    int agg_blocks  = N_NODES / 8;           // 12500 (exact)
    int ee_blocks   = N_EDGES / (8 * 32);    // 6250 (exact)

    // launch #4 = k_ee (ncu capture slot); k_ee is CSR-independent.
    k_hist<<<(N_EDGES + 255) / 256, 256>>>(ei, p_cnt);                   // 1
    k_gemm_dual<<<gemm_blocks, 128>>>(x, 0, p_bnp, Wl, bl, Wr, br,
                                      p_gl, p_gr);                       // 2
    k_scan1<<<NBLK, 1024>>>(p_cnt, p_off, p_bsum);                       // 3
    k_ee<<<ee_blocks, 256>>>(ea, We, p_ee);                              // 4 (profiled)
    k_scan23<<<(N_NODES + 255) / 256, 256>>>(p_off, p_bsum, p_cur);      // 5
    k_scatter<<<(N_EDGES + 255) / 256, 256>>>(ei, p_cur, p_einfo);       // 6

    for (int L = 0; L < 3; L++) {
        if (L > 0) {
            k_gemm_dual<<<gemm_blocks, 128>>>(p_h, 1, p_bnp,
                                              Wl + L * DIM * DIM, bl + L * DIM,
                                              Wr + L * DIM * DIM, br + L * DIM,
                                              p_gl, p_gr);
            k_ee<<<ee_blocks, 256>>>(ea, We + L * EDIM * DIM, p_ee);
        }
        k_aggregate<<<agg_blocks, 256>>>(p_off, p_einfo, p_ee, p_gl, p_gr,
                                         att + L * DIM, bias + L * DIM,
                                         p_h, p_stats);
        k_bn_finalize<<<1, 128>>>(p_stats, gamma + L * DIM, beta + L * DIM, p_bnp);
    }
    k_gemm_final<<<gemm_blocks, 128>>>(p_h, p_bnp, Wf, bf, out);
}